// round 1
// baseline (speedup 1.0000x reference)
#include <cuda_runtime.h>
#include <math.h>

#define B_ 16
#define C_ 512
#define N_ 4096
#define M_ 64

// ---- scratch (static device globals; no runtime allocation) ----
__device__ float g_Q[B_*M_*N_];      // 16 MB, Q then Qn (in place)
__device__ float g_K[B_*M_*N_];      // 16 MB, K then Kn (in place)
__device__ float g_KX[B_*M_*C_];     // 2 MB
__device__ float g_mat[B_*M_*C_];    // 2 MB
__device__ float g_Knsum[B_*M_];
__device__ float g_xsum[B_*C_];
__device__ float g_Vsum[B_*C_];
__device__ float g_tailor[B_*N_];

// ---------------------------------------------------------------
// block-level sum reduction
__device__ __forceinline__ float blk_reduce(float v) {
    __shared__ float s[32];
    int lane = threadIdx.x & 31, w = threadIdx.x >> 5;
#pragma unroll
    for (int o = 16; o; o >>= 1) v += __shfl_xor_sync(0xffffffffu, v, o);
    if (lane == 0) s[w] = v;
    __syncthreads();
    int nw = blockDim.x >> 5;
    v = (threadIdx.x < nw) ? s[threadIdx.x] : 0.f;
    if (w == 0) {
#pragma unroll
        for (int o = 16; o; o >>= 1) v += __shfl_xor_sync(0xffffffffu, v, o);
    }
    return v;  // valid in thread 0
}

// ---------------------------------------------------------------
// xsum[b][c] = sum_n x[b][c][n];  grid (512, 16), 128 thr
__global__ void rowsum_x(const float* __restrict__ x) {
    int row = blockIdx.y * gridDim.x + blockIdx.x;   // b*512 + c
    const float* p = x + (size_t)row * N_;
    float s = 0.f;
    for (int i = threadIdx.x; i < N_; i += blockDim.x) s += p[i];
    s = blk_reduce(s);
    if (threadIdx.x == 0) g_xsum[row] = s;
}

// Knsum[b][m] = sum_n Kn[b][m][n];  grid (64, 16), 128 thr (after norm)
__global__ void rowsum_K() {
    int row = blockIdx.y * gridDim.x + blockIdx.x;   // b*64 + m
    const float* p = g_K + (size_t)row * N_;
    float s = 0.f;
    for (int i = threadIdx.x; i < N_; i += blockDim.x) s += p[i];
    s = blk_reduce(s);
    if (threadIdx.x == 0) g_Knsum[row] = s;
}

// ---------------------------------------------------------------
// Q/K projection: [128(m: 64q + 64k) x 128(n)] tile, K=512.  grid (32, 16), 256 thr
__global__ void qk_gemm(const float* __restrict__ x, const float* __restrict__ Wq,
                        const float* __restrict__ bq, const float* __restrict__ Wk,
                        const float* __restrict__ bk) {
    __shared__ float As[16][132];  // As[k][m]
    __shared__ float Bs[16][132];  // Bs[k][n]
    const int b  = blockIdx.y;
    const int n0 = blockIdx.x * 128;
    const int t  = threadIdx.x;
    const int tm = t >> 4;   // 0..15 (m base)
    const int tn = t & 15;   // 0..15 (n base)
    const float* xb = x + (size_t)b * C_ * N_;
    float acc[8][8];
#pragma unroll
    for (int i = 0; i < 8; i++)
#pragma unroll
        for (int j = 0; j < 8; j++) acc[i][j] = 0.f;

    for (int k0 = 0; k0 < C_; k0 += 16) {
#pragma unroll
        for (int i = 0; i < 8; i++) {
            int idx = t + i * 256;          // 2048 elems of A
            int m = idx >> 4, k = idx & 15;
            As[k][m] = (m < 64) ? Wq[m * C_ + k0 + k] : Wk[(m - 64) * C_ + k0 + k];
        }
#pragma unroll
        for (int i = 0; i < 8; i++) {
            int idx = t + i * 256;          // 2048 elems of B
            int k = idx >> 7, n = idx & 127;
            Bs[k][n] = xb[(size_t)(k0 + k) * N_ + n0 + n];
        }
        __syncthreads();
#pragma unroll
        for (int k = 0; k < 16; k++) {
            float a[8], bb[8];
#pragma unroll
            for (int i = 0; i < 8; i++) a[i]  = As[k][tm + 16 * i];
#pragma unroll
            for (int j = 0; j < 8; j++) bb[j] = Bs[k][tn + 16 * j];
#pragma unroll
            for (int i = 0; i < 8; i++)
#pragma unroll
                for (int j = 0; j < 8; j++) acc[i][j] = fmaf(a[i], bb[j], acc[i][j]);
        }
        __syncthreads();
    }
#pragma unroll
    for (int i = 0; i < 8; i++) {
        int m = tm + 16 * i;
        float bias; float* dst;
        if (m < 64) { bias = bq[m];      dst = g_Q + ((size_t)b * M_ + m) * N_; }
        else        { bias = bk[m - 64]; dst = g_K + ((size_t)b * M_ + (m - 64)) * N_; }
#pragma unroll
        for (int j = 0; j < 8; j++) dst[n0 + tn + 16 * j] = acc[i][j] + bias;
    }
}

// ---------------------------------------------------------------
// per-column L2 normalize (channel dim, 64), in place.  grid (16, 16), 256 thr
__global__ void norm_qk() {
    int b = blockIdx.y;
    int n = blockIdx.x * 256 + threadIdx.x;
    float* Qb = g_Q + (size_t)b * M_ * N_;
    float* Kb = g_K + (size_t)b * M_ * N_;
    float sq = 0.f, sk = 0.f;
#pragma unroll 8
    for (int m = 0; m < 64; m++) {
        float q = Qb[(size_t)m * N_ + n]; sq = fmaf(q, q, sq);
        float k = Kb[(size_t)m * N_ + n]; sk = fmaf(k, k, sk);
    }
    float iq = 1.f / fmaxf(sqrtf(sq), 1e-6f);
    float ik = 1.f / fmaxf(sqrtf(sk), 1e-6f);
#pragma unroll 8
    for (int m = 0; m < 64; m++) {
        Qb[(size_t)m * N_ + n] *= iq;
        Kb[(size_t)m * N_ + n] *= ik;
    }
}

// ---------------------------------------------------------------
// tailor[b][n] = 1 / max(N + sum_m Qn[m][n]*Knsum[m], 1e-6).  grid (16, 16), 256 thr
__global__ void tailor_kernel() {
    __shared__ float ks[64];
    int b = blockIdx.y;
    if (threadIdx.x < 64) ks[threadIdx.x] = g_Knsum[b * 64 + threadIdx.x];
    __syncthreads();
    int n = blockIdx.x * 256 + threadIdx.x;
    const float* Qb = g_Q + (size_t)b * M_ * N_;
    float d = (float)N_;
#pragma unroll 8
    for (int m = 0; m < 64; m++) d = fmaf(Qb[(size_t)m * N_ + n], ks[m], d);
    g_tailor[b * N_ + n] = 1.f / fmaxf(d, 1e-6f);
}

// ---------------------------------------------------------------
// KX[b][m][c] = sum_n Kn[b][m][n] * x[b][c][n].  tile 64x64, K=4096. grid (8, 16), 256 thr
__global__ void kx_gemm(const float* __restrict__ x) {
    __shared__ float As[64][65];
    __shared__ float Bs[64][65];
    int b  = blockIdx.y;
    int c0 = blockIdx.x * 64;
    const float* A  = g_K + (size_t)b * M_ * N_;
    const float* Bm = x + (size_t)b * C_ * N_ + (size_t)c0 * N_;
    int t = threadIdx.x;
    int tm = t >> 4, tc = t & 15;
    float acc[4][4] = {};
    for (int k0 = 0; k0 < N_; k0 += 64) {
#pragma unroll
        for (int i = 0; i < 16; i++) {
            int idx = t + i * 256;
            int r = idx >> 6, kk = idx & 63;
            As[r][kk] = A [(size_t)r * N_ + k0 + kk];
            Bs[r][kk] = Bm[(size_t)r * N_ + k0 + kk];
        }
        __syncthreads();
#pragma unroll
        for (int kk = 0; kk < 64; kk++) {
            float a[4], bb[4];
#pragma unroll
            for (int i = 0; i < 4; i++) a[i]  = As[tm + 16 * i][kk];
#pragma unroll
            for (int j = 0; j < 4; j++) bb[j] = Bs[tc + 16 * j][kk];
#pragma unroll
            for (int i = 0; i < 4; i++)
#pragma unroll
                for (int j = 0; j < 4; j++) acc[i][j] = fmaf(a[i], bb[j], acc[i][j]);
        }
        __syncthreads();
    }
    float* Cp = g_KX + (size_t)b * M_ * C_;
#pragma unroll
    for (int i = 0; i < 4; i++)
#pragma unroll
        for (int j = 0; j < 4; j++)
            Cp[(size_t)(tm + 16 * i) * C_ + c0 + tc + 16 * j] = acc[i][j];
}

// ---------------------------------------------------------------
// mat[b][m][c] = sum_{c'} KX[b][m][c'] * Wv[c][c'] + bv[c]*Knsum[b][m]. grid (8,16), 256 thr
__global__ void mat_gemm(const float* __restrict__ Wv, const float* __restrict__ bv) {
    __shared__ float As[64][65];
    __shared__ float Bs[64][65];
    int b  = blockIdx.y;
    int c0 = blockIdx.x * 64;
    const float* A  = g_KX + (size_t)b * M_ * C_;
    const float* Bm = Wv + (size_t)c0 * C_;
    int t = threadIdx.x;
    int tm = t >> 4, tc = t & 15;
    float acc[4][4] = {};
    for (int k0 = 0; k0 < C_; k0 += 64) {
#pragma unroll
        for (int i = 0; i < 16; i++) {
            int idx = t + i * 256;
            int r = idx >> 6, kk = idx & 63;
            As[r][kk] = A [(size_t)r * C_ + k0 + kk];
            Bs[r][kk] = Bm[(size_t)r * C_ + k0 + kk];
        }
        __syncthreads();
#pragma unroll
        for (int kk = 0; kk < 64; kk++) {
            float a[4], bb[4];
#pragma unroll
            for (int i = 0; i < 4; i++) a[i]  = As[tm + 16 * i][kk];
#pragma unroll
            for (int j = 0; j < 4; j++) bb[j] = Bs[tc + 16 * j][kk];
#pragma unroll
            for (int i = 0; i < 4; i++)
#pragma unroll
                for (int j = 0; j < 4; j++) acc[i][j] = fmaf(a[i], bb[j], acc[i][j]);
        }
        __syncthreads();
    }
    float* Cp = g_mat + (size_t)b * M_ * C_;
#pragma unroll
    for (int i = 0; i < 4; i++) {
        int m = tm + 16 * i;
        float kn = g_Knsum[b * 64 + m];
#pragma unroll
        for (int j = 0; j < 4; j++) {
            int c = c0 + tc + 16 * j;
            Cp[(size_t)m * C_ + c] = acc[i][j] + bv[c] * kn;
        }
    }
}

// ---------------------------------------------------------------
// Vsum[b][c] = Wv[c,:].xsum[b,:] + N*bv[c].  grid (128, 16), 128 thr (warp per c)
__global__ void vsum_kernel(const float* __restrict__ Wv, const float* __restrict__ bv) {
    int b = blockIdx.y;
    int c = blockIdx.x * 4 + (threadIdx.x >> 5);
    int lane = threadIdx.x & 31;
    const float* w  = Wv + (size_t)c * C_;
    const float* xs = g_xsum + b * C_;
    float s = 0.f;
    for (int i = lane; i < C_; i += 32) s = fmaf(w[i], xs[i], s);
#pragma unroll
    for (int o = 16; o; o >>= 1) s += __shfl_xor_sync(0xffffffffu, s, o);
    if (lane == 0) g_Vsum[b * C_ + c] = s + (float)N_ * bv[c];
}

// ---------------------------------------------------------------
// out[b][c][n] = nan_to_num(gamma * tailor[n] * (Vsum[c] + sum_m Qn[m][n]*mat[m][c]))
// grid (64, 8, 16), 256 thr; tile 64c x 64n, K=64
__global__ void final_kernel(float* __restrict__ out, const float* __restrict__ gamma) {
    __shared__ float Ms[64][64];   // Ms[m][cc]
    __shared__ float Qs[64][64];   // Qs[m][nn]
    int b  = blockIdx.z;
    int c0 = blockIdx.y * 64;
    int n0 = blockIdx.x * 64;
    const float* mat = g_mat + (size_t)b * M_ * C_;
    const float* Qb  = g_Q + (size_t)b * M_ * N_;
    int t = threadIdx.x;
#pragma unroll
    for (int i = 0; i < 16; i++) {
        int idx = t + i * 256;
        int m = idx >> 6, cc = idx & 63;
        Ms[m][cc] = mat[(size_t)m * C_ + c0 + cc];
        Qs[m][cc] = Qb [(size_t)m * N_ + n0 + cc];
    }
    __syncthreads();
    int tc = t >> 4, tn = t & 15;
    float acc[4][4] = {};
#pragma unroll
    for (int m = 0; m < 64; m++) {
        float a[4], bb[4];
#pragma unroll
        for (int i = 0; i < 4; i++) a[i]  = Ms[m][tc + 16 * i];
#pragma unroll
        for (int j = 0; j < 4; j++) bb[j] = Qs[m][tn + 16 * j];
#pragma unroll
        for (int i = 0; i < 4; i++)
#pragma unroll
            for (int j = 0; j < 4; j++) acc[i][j] = fmaf(a[i], bb[j], acc[i][j]);
    }
    float g = gamma[0];
    const float* vs = g_Vsum + b * C_;
    const float* tl = g_tailor + (size_t)b * N_;
#pragma unroll
    for (int i = 0; i < 4; i++) {
        int c = c0 + tc + 16 * i;
        float vsum = vs[c];
        float* orow = out + ((size_t)b * C_ + c) * N_;
#pragma unroll
        for (int j = 0; j < 4; j++) {
            int n = n0 + tn + 16 * j;
            float val = g * tl[n] * (vsum + acc[i][j]);
            if (isnan(val)) val = 0.f;
            else if (isinf(val)) val = val > 0.f ? 1.f : -1.f;
            orow[n] = val;
        }
    }
}

// ---------------------------------------------------------------
extern "C" void kernel_launch(void* const* d_in, const int* in_sizes, int n_in,
                              void* d_out, int out_size) {
    const float* x     = (const float*)d_in[0];
    const float* Wq    = (const float*)d_in[1];
    const float* bq    = (const float*)d_in[2];
    const float* Wk    = (const float*)d_in[3];
    const float* bk    = (const float*)d_in[4];
    const float* Wv    = (const float*)d_in[5];
    const float* bv    = (const float*)d_in[6];
    const float* gamma = (const float*)d_in[7];
    float* out = (float*)d_out;

    rowsum_x    <<<dim3(512, 16), 128>>>(x);
    qk_gemm     <<<dim3(32, 16), 256>>>(x, Wq, bq, Wk, bk);
    norm_qk     <<<dim3(16, 16), 256>>>();
    rowsum_K    <<<dim3(64, 16), 128>>>();
    tailor_kernel<<<dim3(16, 16), 256>>>();
    kx_gemm     <<<dim3(8, 16), 256>>>(x);
    mat_gemm    <<<dim3(8, 16), 256>>>(Wv, bv);
    vsum_kernel <<<dim3(128, 16), 128>>>(Wv, bv);
    final_kernel<<<dim3(64, 8, 16), 256>>>(out, gamma);
}